// round 16
// baseline (speedup 1.0000x reference)
#include <cuda_runtime.h>
#include <cstdint>

// imgs (B,L,M,C,H,W) f32, ts2img_weights (B,L,M) f32
// out (B,L,K,H,W) f32: out[b,l,k] = s * imgs[b,l,topk_idx(k),0]
// s = (1 - w_sel) + w_sel. Non-selected straight-through terms are exactly 0.
//
// Perf model: memory path ~13.6us with policy cache hints (R15 ncu); the
// timed 14.85us included a second launch + dependency gap. This round fuses
// the top-k into the gather (recomputed per micro-chunk, ~30 ALU ops vs an
// 8KB copy) -> single kernel, single launch.

#define B_ 32
#define L_ 7
#define M_ 6
#define C_ 3
#define H_ 128
#define W_ 128
#define K_ 3
#define HW_ (H_ * W_)                        // 16384 floats per slice
#define NSLICE_ (B_ * L_ * K_)               // 672
#define THREADS_ 256
#define MC_F_ 2048                           // micro-chunk floats (8 KB)
#define MC_PER_SLICE_ (HW_ / MC_F_)          // 8
#define NMC_ (NSLICE_ * MC_PER_SLICE_)       // 5376 micro-chunks
#define GRID_ (148 * 8)                      // single wave @occ 8
#define V8_ITERS_ (MC_F_ / 8 / THREADS_)     // 1 x 256-bit op per thread/iter

__global__ __launch_bounds__(THREADS_) void mt2v_fused_kernel(
    const float* __restrict__ imgs,
    const float* __restrict__ wts,
    float* __restrict__ out)
{
    const int t = threadIdx.x;

    // Policy descriptors (non-advisory cache_hint path) — proven in R15.
    uint64_t pol_ld, pol_st;
    asm("createpolicy.fractional.L2::evict_last.b64 %0, 1.0;"  : "=l"(pol_ld));
    asm("createpolicy.fractional.L2::evict_first.b64 %0, 1.0;" : "=l"(pol_st));

    for (int c = blockIdx.x; c < NMC_; c += GRID_) {
        const int slice = c / MC_PER_SLICE_;
        const int mc    = c % MC_PER_SLICE_;
        const int k     = slice % K_;
        const int bl    = slice / K_;

        // Inline top-k: 6 L1-hot loads + ~30 ALU ops (vs 8KB of copy work).
        float wv[M_];
#pragma unroll
        for (int m = 0; m < M_; m++) wv[m] = __ldg(&wts[bl * M_ + m]);

        // Stable top-k (strict > => lowest index wins ties, per lax.top_k).
        int sel = 0;
        bool used[M_];
#pragma unroll
        for (int m = 0; m < M_; m++) used[m] = false;
#pragma unroll
        for (int kk = 0; kk < K_; kk++) {
            float best = -3.402823466e+38f;
            int bi = 0;
#pragma unroll
            for (int m = 0; m < M_; m++)
                if (!used[m] && wv[m] > best) { best = wv[m]; bi = m; }
            used[bi] = true;
            if (kk == k) sel = bi;
        }
        const float s = (1.0f - wv[sel]) + wv[sel];

        const char* src = (const char*)(imgs
                          + (size_t)(bl * M_ + sel) * (size_t)(C_ * HW_))
                        + (size_t)mc * (MC_F_ * 4) + (size_t)t * 32;
        char* dst = (char*)out + (size_t)slice * (HW_ * 4)
                  + (size_t)mc * (MC_F_ * 4) + (size_t)t * 32;

#pragma unroll
        for (int i = 0; i < V8_ITERS_; i++) {
            uint32_t r0, r1, r2, r3, r4, r5, r6, r7;
            asm("ld.global.nc.L2::cache_hint.v8.b32 "
                "{%0,%1,%2,%3,%4,%5,%6,%7}, [%8], %9;"
                : "=r"(r0), "=r"(r1), "=r"(r2), "=r"(r3),
                  "=r"(r4), "=r"(r5), "=r"(r6), "=r"(r7)
                : "l"(src + (size_t)i * (THREADS_ * 32)), "l"(pol_ld));

            r0 = __float_as_uint(__uint_as_float(r0) * s);
            r1 = __float_as_uint(__uint_as_float(r1) * s);
            r2 = __float_as_uint(__uint_as_float(r2) * s);
            r3 = __float_as_uint(__uint_as_float(r3) * s);
            r4 = __float_as_uint(__uint_as_float(r4) * s);
            r5 = __float_as_uint(__uint_as_float(r5) * s);
            r6 = __float_as_uint(__uint_as_float(r6) * s);
            r7 = __float_as_uint(__uint_as_float(r7) * s);

            asm volatile("st.global.L2::cache_hint.v8.b32 "
                         "[%0], {%1,%2,%3,%4,%5,%6,%7,%8}, %9;"
                         :: "l"(dst + (size_t)i * (THREADS_ * 32)),
                            "r"(r0), "r"(r1), "r"(r2), "r"(r3),
                            "r"(r4), "r"(r5), "r"(r6), "r"(r7),
                            "l"(pol_st)
                         : "memory");
        }
    }
}

extern "C" void kernel_launch(void* const* d_in, const int* in_sizes, int n_in,
                              void* d_out, int out_size)
{
    const float* imgs = (const float*)d_in[0];
    const float* wts  = (const float*)d_in[1];
    float* out        = (float*)d_out;

    mt2v_fused_kernel<<<GRID_, THREADS_>>>(imgs, wts, out);
}

// round 17
// speedup vs baseline: 1.4068x; 1.4068x over previous
#include <cuda_runtime.h>
#include <cstdint>

// imgs (B,L,M,C,H,W) f32, ts2img_weights (B,L,M) f32
// out (B,L,K,H,W) f32: out[b,l,k] = s * imgs[b,l,topk_idx(k),0]
// s = (1 - w_sel) + w_sel. Non-selected straight-through terms are exactly 0.
//
// Structure (R15+R16 lessons): single launch; each block builds the full
// 672-entry descriptor table in SMEM once (cheap, concurrent), then runs the
// proven 13.6us policy-hinted persistent gather loop against SMEM descs.

#define B_ 32
#define L_ 7
#define M_ 6
#define C_ 3
#define H_ 128
#define W_ 128
#define K_ 3
#define HW_ (H_ * W_)                        // 16384 floats per slice
#define NSLICE_ (B_ * L_ * K_)               // 672
#define THREADS_ 256
#define MC_F_ 2048                           // micro-chunk floats (8 KB)
#define MC_PER_SLICE_ (HW_ / MC_F_)          // 8
#define NMC_ (NSLICE_ * MC_PER_SLICE_)       // 5376 micro-chunks
#define GRID_ (148 * 8)                      // single wave @occ 8
#define V8_ITERS_ (MC_F_ / 8 / THREADS_)     // 1 x 256-bit op per thread/iter

__global__ __launch_bounds__(THREADS_) void mt2v_fused_kernel(
    const float* __restrict__ imgs,
    const float* __restrict__ wts,
    float* __restrict__ out)
{
    __shared__ int   s_off[NSLICE_];   // src float-offset per slice
    __shared__ float s_scl[NSLICE_];   // scale per slice

    const int t = threadIdx.x;

    // ---- Preamble: build all 672 descriptors in SMEM (~3 per thread) ------
    for (int idx = t; idx < NSLICE_; idx += THREADS_) {
        const int k  = idx % K_;
        const int bl = idx / K_;

        float wv[M_];
#pragma unroll
        for (int m = 0; m < M_; m++) wv[m] = __ldg(&wts[bl * M_ + m]);

        // Branchless stable top-k via rank counting (ties -> lower index).
        int sel = 0;
        float ssc = 0.0f;
#pragma unroll
        for (int m = 0; m < M_; m++) {
            int rank = 0;
#pragma unroll
            for (int j = 0; j < M_; j++)
                rank += (wv[j] > wv[m]) || ((wv[j] == wv[m]) && (j < m));
            if (rank == k) { sel = m; ssc = (1.0f - wv[m]) + wv[m]; }
        }

        s_off[idx] = (bl * M_ + sel) * (C_ * HW_);
        s_scl[idx] = ssc;
    }
    __syncthreads();

    // Policy descriptors: input evict_last (retain), output evict_first.
    uint64_t pol_ld, pol_st;
    asm("createpolicy.fractional.L2::evict_last.b64 %0, 1.0;"  : "=l"(pol_ld));
    asm("createpolicy.fractional.L2::evict_first.b64 %0, 1.0;" : "=l"(pol_st));

    // ---- Main loop: identical to the proven 13.6us gather -----------------
    for (int c = blockIdx.x; c < NMC_; c += GRID_) {
        const int slice = c / MC_PER_SLICE_;
        const int mc    = c % MC_PER_SLICE_;

        const float s   = s_scl[slice];
        const int   off = s_off[slice];

        const char* src = (const char*)(imgs + (size_t)off)
                        + (size_t)mc * (MC_F_ * 4) + (size_t)t * 32;
        char* dst = (char*)out + (size_t)slice * (HW_ * 4)
                  + (size_t)mc * (MC_F_ * 4) + (size_t)t * 32;

#pragma unroll
        for (int i = 0; i < V8_ITERS_; i++) {
            uint32_t r0, r1, r2, r3, r4, r5, r6, r7;
            asm("ld.global.nc.L2::cache_hint.v8.b32 "
                "{%0,%1,%2,%3,%4,%5,%6,%7}, [%8], %9;"
                : "=r"(r0), "=r"(r1), "=r"(r2), "=r"(r3),
                  "=r"(r4), "=r"(r5), "=r"(r6), "=r"(r7)
                : "l"(src + (size_t)i * (THREADS_ * 32)), "l"(pol_ld));

            r0 = __float_as_uint(__uint_as_float(r0) * s);
            r1 = __float_as_uint(__uint_as_float(r1) * s);
            r2 = __float_as_uint(__uint_as_float(r2) * s);
            r3 = __float_as_uint(__uint_as_float(r3) * s);
            r4 = __float_as_uint(__uint_as_float(r4) * s);
            r5 = __float_as_uint(__uint_as_float(r5) * s);
            r6 = __float_as_uint(__uint_as_float(r6) * s);
            r7 = __float_as_uint(__uint_as_float(r7) * s);

            asm volatile("st.global.L2::cache_hint.v8.b32 "
                         "[%0], {%1,%2,%3,%4,%5,%6,%7,%8}, %9;"
                         :: "l"(dst + (size_t)i * (THREADS_ * 32)),
                            "r"(r0), "r"(r1), "r"(r2), "r"(r3),
                            "r"(r4), "r"(r5), "r"(r6), "r"(r7),
                            "l"(pol_st)
                         : "memory");
        }
    }
}

extern "C" void kernel_launch(void* const* d_in, const int* in_sizes, int n_in,
                              void* d_out, int out_size)
{
    const float* imgs = (const float*)d_in[0];
    const float* wts  = (const float*)d_in[1];
    float* out        = (float*)d_out;

    mt2v_fused_kernel<<<GRID_, THREADS_>>>(imgs, wts, out);
}